// round 6
// baseline (speedup 1.0000x reference)
#include <cuda_runtime.h>

typedef unsigned long long ull;

#define C_DIM 1024
#define TPB   256
#define TILE_R 128
#define PAD  130           // row stride for transposed activation buffers

// smem arena layout (floats)
#define SM_XT 0                         // [128][130] x clipped(+-5), transposed: XT[k][row]
#define SM_XH (128*PAD)                 // [64][130]  raw ht, transposed
#define SM_WD (SM_XH + 64*PAD)          // [64][128]  duplicated weight tile (w,w) pairs
#define SM_B1 (SM_WD + 64*128)          // [64][130]
#define SM_B2 (SM_B1 + 64*PAD)
#define SM_B3 (SM_B2 + 64*PAD)
#define SM_TOT (SM_B3 + 64*PAD)         // 58112 floats = 232448 B

__device__ float g_adj[2 * C_DIM];

__device__ __forceinline__ float4 ldg4(const float* p) {
    return __ldg(reinterpret_cast<const float4*>(p));
}
__device__ __forceinline__ float clipf(float v, float lo, float hi) {
    return fminf(fmaxf(v, lo), hi);
}
__device__ __forceinline__ float sigm(float x) { return 1.f / (1.f + expf(-x)); }

__device__ __forceinline__ void ffma2(ull& d, ull a, ull b) {
    asm("fma.rn.f32x2 %0, %1, %2, %0;" : "+l"(d) : "l"(a), "l"(b));
}
__device__ __forceinline__ ull pk(float x, float y) {
    ull v; asm("mov.b64 %0, {%1, %2};" : "=l"(v) : "f"(x), "f"(y)); return v;
}
__device__ __forceinline__ float2 upk(ull v) {
    float2 r; asm("mov.b64 {%0, %1}, %2;" : "=f"(r.x), "=f"(r.y) : "l"(v)); return r;
}

// acc[u2] covers output o = 2*tx + 16*(u2>>1) + (u2&1)
#define OUT_OF(u2) (2 * tx + (((u2) >> 1) << 4) + ((u2) & 1))

// ---------------------------------------------------------------------------
// adj pre-kernel
// ---------------------------------------------------------------------------
__global__ void gkt_adj(const int* __restrict__ qt, const float* __restrict__ onehot,
                        const float* __restrict__ graphs) {
    __shared__ int nz[C_DIM];
    __shared__ int wcnt[32];
    __shared__ int woff[33];
    const int t = threadIdx.x, wid = t >> 5, lane = t & 31;
    const int q0 = qt[0];
    const bool on = (onehot[(long)q0 * C_DIM + t] > 0.5f);
    unsigned bal = __ballot_sync(0xffffffffu, on);
    if (lane == 0) wcnt[wid] = __popc(bal);
    __syncthreads();
    if (t == 0) { int s = 0; for (int w = 0; w < 32; ++w) { woff[w] = s; s += wcnt[w]; } woff[32] = s; }
    __syncthreads();
    if (on) nz[woff[wid] + __popc(bal & ((1u << lane) - 1u))] = t;
    __syncthreads();
    const int n = woff[32];
    const float denom = fmaxf((float)n, 1.f);
#pragma unroll
    for (int k = 0; k < 2; ++k) {
        float s = 0.f;
        for (int idx = 0; idx < n; ++idx)
            s += graphs[k * C_DIM * C_DIM + nz[idx] * C_DIM + t];
        g_adj[k * C_DIM + t] = clipf(s / denom, -5.f, 5.f);
    }
}

// ---------------------------------------------------------------------------
// helpers
// ---------------------------------------------------------------------------

// Stage a 64x64 weight tile into WD with (w,w) duplication, float4-granular.
// Output o's duplicated pair sits at WD[kk*128 + 2*o .. 2*o+1].
__device__ __forceinline__ void stage_w(float* __restrict__ WD, const float* __restrict__ src,
                                        int rstride, int t) {
#pragma unroll
    for (int i = t; i < 64 * 16; i += TPB) {
        int kk = i >> 4, o4 = i & 15;                  // group of 4 outputs
        float4 w = ldg4(src + kk * rstride + o4 * 4);
        float4* dst = reinterpret_cast<float4*>(WD + kk * 128 + o4 * 8);
        dst[0] = make_float4(w.x, w.x, w.y, w.y);
        dst[1] = make_float4(w.z, w.z, w.w, w.w);
    }
}

// acc += A(rows) x W(outs): thread = 4 rows (2 f32x2 row-pairs) x 8 outs.
// b fetched as LDS.128 = two duplicated pairs -> 6 LDS per k-step total.
// k-row of WD = 128 floats = 32 ulonglong2; thread tx owns u2-index tx (+8u).
__device__ __forceinline__ void gemm_acc(const float* __restrict__ A, const float* __restrict__ WD,
                                         int ty, int tx, ull acc[8][2]) {
    const float* Ab = A + ty * 4;
    const ulonglong2* Wb = reinterpret_cast<const ulonglong2*>(WD) + tx;
#pragma unroll 8
    for (int kk = 0; kk < 64; ++kk) {
        ull a0 = *reinterpret_cast<const ull*>(Ab + kk * PAD);
        ull a1 = *reinterpret_cast<const ull*>(Ab + kk * PAD + 2);
        const ulonglong2* wk = Wb + kk * 32;           // 32 ulonglong2 = 128 floats per k-row
#pragma unroll
        for (int u = 0; u < 4; ++u) {
            ulonglong2 b = wk[u * 8];                  // +16 outputs = +32 floats = +8 u2
            ffma2(acc[2 * u][0],     a0, b.x);
            ffma2(acc[2 * u][1],     a1, b.x);
            ffma2(acc[2 * u + 1][0], a0, b.y);
            ffma2(acc[2 * u + 1][1], a1, b.y);
        }
    }
}

__device__ __forceinline__ void init_bias(ull acc[8][2], const float* __restrict__ b1p,
                                          const float* __restrict__ b2p, int tx) {
#pragma unroll
    for (int u = 0; u < 8; ++u) {
        int o = OUT_OF(u);
        float v = __ldg(b1p + o);
        if (b2p) v += __ldg(b2p + o);
        ull pv = pk(v, v);
        acc[u][0] = pv; acc[u][1] = pv;
    }
}

// ---------------------------------------------------------------------------
// fused main kernel
// ---------------------------------------------------------------------------
__global__ __launch_bounds__(TPB, 1) void gkt_main(
    const int*   __restrict__ qt,     const float* __restrict__ ht,
    const float* __restrict__ onehot, const float* __restrict__ kc,
    const float* __restrict__ nw_ptr,
    const float* __restrict__ Ws1, const float* __restrict__ bs1,
    const float* __restrict__ Ws2, const float* __restrict__ bs2,
    const float* __restrict__ Wn1, const float* __restrict__ bn1,
    const float* __restrict__ Wn2, const float* __restrict__ bn2,
    const float* __restrict__ ea_w,
    const float* __restrict__ We,  const float* __restrict__ be,
    const float* __restrict__ Wa,  const float* __restrict__ ba,
    const float* __restrict__ W_ih, const float* __restrict__ b_ih,
    const float* __restrict__ W_hh, const float* __restrict__ b_hh,
    const float* __restrict__ Wp,  const float* __restrict__ bp,
    float* __restrict__ out)
{
    extern __shared__ float sm[];
    float* XT = sm + SM_XT;
    float* XH = sm + SM_XH;
    float* WD = sm + SM_WD;
    float* B1 = sm + SM_B1;
    float* B2 = sm + SM_B2;
    float* B3 = sm + SM_B3;
    float* B4 = XT;                 // XT region reused after self fix-up
    float* tmp = WD;                // fix-up scratch
    int*   mlist = (int*)(WD + 64);
    int*   mcnt  = (int*)(WD + 192);

    const int t  = threadIdx.x;
    const int tx = t & 7, ty = t >> 3;        // rows = ty*4 .. ty*4+3
    const int row0 = blockIdx.x * TILE_R;
    const int b  = row0 >> 10;
    const int c0 = row0 & (C_DIM - 1);
    const int q  = __ldg(&qt[b]);

    // ---- stage X transposed: XT clipped(+-5), XH raw ht ----
#pragma unroll
    for (int i = t; i < TILE_R * 64; i += TPB) {
        int row = i >> 6, k = i & 63;
        float hv = ht[(row0 + row) * 64 + k];
        XH[k * PAD + row] = hv;
        XT[k * PAD + row] = clipf(hv, -5.f, 5.f);
        XT[(64 + k) * PAD + row] = clipf(kc[(c0 + row) * 64 + k], -5.f, 5.f);
    }

    ull acc[8][2];
    const float wcl = clipf(__ldg(nw_ptr), 0.1f, 0.9f);

    // ================= stage 1: H1(k=0) = relu(X @ Wn1[0][128:256]) ========
    init_bias(acc, bn1, nullptr, tx);
    __syncthreads();
    stage_w(WD, Wn1 + (0 * 256 + 128) * 64, 64, t);
    __syncthreads();
    gemm_acc(XT, WD, ty, tx, acc);
    __syncthreads();
    stage_w(WD, Wn1 + (0 * 256 + 192) * 64, 64, t);
    __syncthreads();
    gemm_acc(XT + 64 * PAD, WD, ty, tx, acc);
#pragma unroll
    for (int u = 0; u < 8; ++u) {
        int o = OUT_OF(u);
#pragma unroll
        for (int p = 0; p < 2; ++p) {
            float2 v = upk(acc[u][p]);
            *reinterpret_cast<float2*>(B1 + o * PAD + ty * 4 + 2 * p) =
                make_float2(fmaxf(v.x, 0.f), fmaxf(v.y, 0.f));
        }
    }

    // ================= stage 2: nf0 = clip5(aj0 * clip5(relu(H1 @ Wn2[0]))) =
    init_bias(acc, bn2, nullptr, tx);
    __syncthreads();
    stage_w(WD, Wn2, 64, t);
    __syncthreads();
    gemm_acc(B1, WD, ty, tx, acc);
#pragma unroll
    for (int u = 0; u < 8; ++u) {
        int o = OUT_OF(u);
#pragma unroll
        for (int p = 0; p < 2; ++p) {
            float2 v = upk(acc[u][p]);
            int r = ty * 4 + 2 * p;
            float a0 = __ldg(&g_adj[c0 + r]), a1 = __ldg(&g_adj[c0 + r + 1]);
            float nb0x = fminf(fmaxf(v.x, 0.f), 5.f);
            float nb0y = fminf(fmaxf(v.y, 0.f), 5.f);
            *reinterpret_cast<float2*>(B2 + o * PAD + r) =
                make_float2(clipf(a0 * nb0x, -5.f, 5.f), clipf(a1 * nb0y, -5.f, 5.f));
        }
    }

    // ================= stage 3: H1(k=1) ====================================
    init_bias(acc, bn1 + 64, nullptr, tx);
    __syncthreads();
    stage_w(WD, Wn1 + (1 * 256 + 128) * 64, 64, t);
    __syncthreads();
    gemm_acc(XT, WD, ty, tx, acc);
    __syncthreads();
    stage_w(WD, Wn1 + (1 * 256 + 192) * 64, 64, t);
    __syncthreads();
    gemm_acc(XT + 64 * PAD, WD, ty, tx, acc);
#pragma unroll
    for (int u = 0; u < 8; ++u) {
        int o = OUT_OF(u);
#pragma unroll
        for (int p = 0; p < 2; ++p) {
            float2 v = upk(acc[u][p]);
            *reinterpret_cast<float2*>(B1 + o * PAD + ty * 4 + 2 * p) =
                make_float2(fmaxf(v.x, 0.f), fmaxf(v.y, 0.f));
        }
    }

    // ================= stage 4: nf = clip5(w*nf0 + (1-w)*aj1*nb1) ==========
    init_bias(acc, bn2 + 64, nullptr, tx);
    __syncthreads();
    stage_w(WD, Wn2 + 64 * 64, 64, t);
    __syncthreads();
    gemm_acc(B1, WD, ty, tx, acc);
#pragma unroll
    for (int u = 0; u < 8; ++u) {
        int o = OUT_OF(u);
#pragma unroll
        for (int p = 0; p < 2; ++p) {
            float2 v = upk(acc[u][p]);
            int r = ty * 4 + 2 * p;
            float a1x = __ldg(&g_adj[C_DIM + c0 + r]), a1y = __ldg(&g_adj[C_DIM + c0 + r + 1]);
            float2 nf0 = *reinterpret_cast<float2*>(B2 + o * PAD + r);
            float nb1x = fminf(fmaxf(v.x, 0.f), 5.f);
            float nb1y = fminf(fmaxf(v.y, 0.f), 5.f);
            float nfx = clipf(wcl * nf0.x + (1.f - wcl) * a1x * nb1x, -5.f, 5.f);
            float nfy = clipf(wcl * nf0.y + (1.f - wcl) * a1y * nb1y, -5.f, 5.f);
            *reinterpret_cast<float2*>(B2 + o * PAD + r) = make_float2(nfx, nfy);
        }
    }

    // ================= stage 5: masked-row self-MLP fix-up ==================
    __syncthreads();
    if (t == 0) *mcnt = 0;
    __syncthreads();
    if (t < TILE_R) {
        float m = __ldg(&onehot[(long)q * C_DIM + c0 + t]);
        if (m > 0.5f) { int pos = atomicAdd(mcnt, 1); mlist[pos] = t; }
    }
    __syncthreads();
    const int nm = *mcnt;
    for (int idx = 0; idx < nm; ++idx) {
        int row = mlist[idx];
        if (t < 64) {
            float a = __ldg(bs1 + t);
            for (int k = 0; k < 64; ++k)   a += XH[k * PAD + row] * __ldg(Ws1 + k * 64 + t);
            for (int k = 64; k < 128; ++k) a += XT[k * PAD + row] * __ldg(Ws1 + k * 64 + t);
            tmp[t] = fmaxf(a, 0.f);
        }
        __syncthreads();
        if (t < 64) {
            float a = __ldg(bs2 + t);
            for (int k = 0; k < 64; ++k) a += tmp[k] * __ldg(Ws2 + k * 64 + t);
            B2[t * PAD + row] = clipf(fmaxf(a, 0.f), -10.f, 10.f);
        }
        __syncthreads();
    }
    // B2 now holds m_next (mn)

    // ================= stage 6: sigE = sigmoid(mn @ We + be) -> B1 =========
    init_bias(acc, be, nullptr, tx);
    __syncthreads();
    stage_w(WD, We, 64, t);
    __syncthreads();
    gemm_acc(B2, WD, ty, tx, acc);
#pragma unroll
    for (int u = 0; u < 8; ++u) {
        int o = OUT_OF(u);
#pragma unroll
        for (int p = 0; p < 2; ++p) {
            float2 v = upk(acc[u][p]);
            *reinterpret_cast<float2*>(B1 + o * PAD + ty * 4 + 2 * p) =
                make_float2(sigm(v.x), sigm(v.y));
        }
    }

    // ================= stage 7: res = mn - g*sigE*mn + g*tanh(mn@Wa+ba) -> B3
    init_bias(acc, ba, nullptr, tx);
    __syncthreads();
    stage_w(WD, Wa, 64, t);
    __syncthreads();
    gemm_acc(B2, WD, ty, tx, acc);
#pragma unroll
    for (int u = 0; u < 8; ++u) {
        int o = OUT_OF(u);
#pragma unroll
        for (int p = 0; p < 2; ++p) {
            float2 v = upk(acc[u][p]);
            int r = ty * 4 + 2 * p;
            float gx = __ldg(&ea_w[c0 + r]), gy = __ldg(&ea_w[c0 + r + 1]);
            float2 mn = *reinterpret_cast<float2*>(B2 + o * PAD + r);
            float2 sg = *reinterpret_cast<float2*>(B1 + o * PAD + r);
            float rx = mn.x - gx * sg.x * mn.x + gx * tanhf(v.x);
            float ry = mn.y - gy * sg.y * mn.y + gy * tanhf(v.y);
            *reinterpret_cast<float2*>(B3 + o * PAD + r) = make_float2(rx, ry);
        }
    }

    // ================= stage 8: r gate -> B1 ================================
    init_bias(acc, b_ih, b_hh, tx);
    __syncthreads();
    stage_w(WD, W_ih, 192, t);
    __syncthreads();
    gemm_acc(B3, WD, ty, tx, acc);
    __syncthreads();
    stage_w(WD, W_hh, 192, t);
    __syncthreads();
    gemm_acc(XH, WD, ty, tx, acc);
#pragma unroll
    for (int u = 0; u < 8; ++u) {
        int o = OUT_OF(u);
#pragma unroll
        for (int p = 0; p < 2; ++p) {
            float2 v = upk(acc[u][p]);
            *reinterpret_cast<float2*>(B1 + o * PAD + ty * 4 + 2 * p) =
                make_float2(sigm(v.x), sigm(v.y));
        }
    }

    // ================= stage 9: z gate -> B2 (mn dead) ======================
    init_bias(acc, b_ih + 64, b_hh + 64, tx);
    __syncthreads();
    stage_w(WD, W_ih + 64, 192, t);
    __syncthreads();
    gemm_acc(B3, WD, ty, tx, acc);
    __syncthreads();
    stage_w(WD, W_hh + 64, 192, t);
    __syncthreads();
    gemm_acc(XH, WD, ty, tx, acc);
#pragma unroll
    for (int u = 0; u < 8; ++u) {
        int o = OUT_OF(u);
#pragma unroll
        for (int p = 0; p < 2; ++p) {
            float2 v = upk(acc[u][p]);
            *reinterpret_cast<float2*>(B2 + o * PAD + ty * 4 + 2 * p) =
                make_float2(sigm(v.x), sigm(v.y));
        }
    }

    // ================= stage 10a: hn = ht@Whhn + bhhn -> B4 (XT reuse) =====
    init_bias(acc, b_hh + 128, nullptr, tx);
    __syncthreads();
    stage_w(WD, W_hh + 128, 192, t);
    __syncthreads();
    gemm_acc(XH, WD, ty, tx, acc);
#pragma unroll
    for (int u = 0; u < 8; ++u) {
        int o = OUT_OF(u);
#pragma unroll
        for (int p = 0; p < 2; ++p) {
            float2 v = upk(acc[u][p]);
            *reinterpret_cast<float2*>(B4 + o * PAD + ty * 4 + 2 * p) = make_float2(v.x, v.y);
        }
    }

    // ================= stage 10b: n, h_next -> B1 ==========================
    init_bias(acc, b_ih + 128, nullptr, tx);
    __syncthreads();
    stage_w(WD, W_ih + 128, 192, t);
    __syncthreads();
    gemm_acc(B3, WD, ty, tx, acc);
#pragma unroll
    for (int u = 0; u < 8; ++u) {
        int o = OUT_OF(u);
#pragma unroll
        for (int p = 0; p < 2; ++p) {
            float2 v = upk(acc[u][p]);
            int r = ty * 4 + 2 * p;
            float2 hn = *reinterpret_cast<float2*>(B4 + o * PAD + r);
            float2 rr = *reinterpret_cast<float2*>(B1 + o * PAD + r);
            float2 zz = *reinterpret_cast<float2*>(B2 + o * PAD + r);
            float2 hv = *reinterpret_cast<float2*>(XH + o * PAD + r);
            float nx = tanhf(v.x + rr.x * hn.x);
            float ny = tanhf(v.y + rr.y * hn.y);
            float hx = (1.f - zz.x) * nx + zz.x * hv.x;
            float hy = (1.f - zz.y) * ny + zz.y * hv.y;
            *reinterpret_cast<float2*>(B1 + o * PAD + r) = make_float2(hx, hy);
        }
    }

    // ================= stage 11: y = sigm(h_next @ Wp + bp) ================
    __syncthreads();
    {
        int row = t >> 1, half = t & 1;
        float s = 0.f;
        const float* hb = B1 + half * 32 * PAD + row;
#pragma unroll
        for (int o = 0; o < 32; ++o)
            s += hb[o * PAD] * __ldg(Wp + half * 32 + o);
        s += __shfl_xor_sync(0xffffffffu, s, 1);
        if (half == 0)
            out[row0 + row] = sigm(s + __ldg(bp));
    }
}

extern "C" void kernel_launch(void* const* d_in, const int* in_sizes, int n_in,
                              void* d_out, int out_size) {
    const int*   qt     = (const int*)  d_in[1];
    const float* ht     = (const float*)d_in[2];
    const float* onehot = (const float*)d_in[3];
    const float* kc     = (const float*)d_in[4];
    const float* graphs = (const float*)d_in[5];
    const float* nw     = (const float*)d_in[6];
    const float* Ws1    = (const float*)d_in[7];
    const float* bs1    = (const float*)d_in[8];
    const float* Ws2    = (const float*)d_in[9];
    const float* bs2    = (const float*)d_in[10];
    const float* Wn1    = (const float*)d_in[11];
    const float* bn1    = (const float*)d_in[12];
    const float* Wn2    = (const float*)d_in[13];
    const float* bn2    = (const float*)d_in[14];
    const float* ea_w   = (const float*)d_in[15];
    const float* We     = (const float*)d_in[16];
    const float* be     = (const float*)d_in[17];
    const float* Wa     = (const float*)d_in[18];
    const float* ba     = (const float*)d_in[19];
    const float* W_ih   = (const float*)d_in[20];
    const float* b_ih   = (const float*)d_in[21];
    const float* W_hh   = (const float*)d_in[22];
    const float* b_hh   = (const float*)d_in[23];
    const float* Wp     = (const float*)d_in[24];
    const float* bp     = (const float*)d_in[25];
    float* out = (float*)d_out;

    gkt_adj<<<1, 1024>>>(qt, onehot, graphs);

    const int smem_bytes = SM_TOT * (int)sizeof(float);   // 232448 B
    cudaFuncSetAttribute(gkt_main, cudaFuncAttributeMaxDynamicSharedMemorySize, smem_bytes);
    const int nrows = 256 * C_DIM;
    gkt_main<<<nrows / TILE_R, TPB, smem_bytes>>>(
        qt, ht, onehot, kc, nw,
        Ws1, bs1, Ws2, bs2, Wn1, bn1, Wn2, bn2,
        ea_w, We, be, Wa, ba, W_ih, b_ih, W_hh, b_hh, Wp, bp,
        out);
}

// round 7
// speedup vs baseline: 1.3349x; 1.3349x over previous
#include <cuda_runtime.h>

typedef unsigned long long ull;

#define C_DIM 1024
#define TPB   256
#define TILE_R 128
#define PAD  132           // row stride (floats) for transposed activation buffers; %4==0 for LDS.128

// smem arena layout (floats)
#define SM_XT 0                         // [128][PAD] x clipped(+-5), transposed: XT[k][row]
#define SM_XH (128*PAD)                 // [64][PAD]  raw ht, transposed
#define SM_WD (SM_XH + 64*PAD)          // [64][64]   natural-layout weight tile
#define SM_B1 (SM_WD + 64*64)           // [64][PAD]
#define SM_B2 (SM_B1 + 64*PAD)
#define SM_B3 (SM_B2 + 64*PAD)
#define SM_TOT (SM_B3 + 64*PAD)         // 54784 floats = 219136 B

__device__ float g_adj[2 * C_DIM];

__device__ __forceinline__ float4 ldg4(const float* p) {
    return __ldg(reinterpret_cast<const float4*>(p));
}
__device__ __forceinline__ float clipf(float v, float lo, float hi) {
    return fminf(fmaxf(v, lo), hi);
}
__device__ __forceinline__ float sigm(float x) { return 1.f / (1.f + expf(-x)); }

__device__ __forceinline__ void ffma2(ull& d, ull a, ull b) {
    asm("fma.rn.f32x2 %0, %1, %2, %0;" : "+l"(d) : "l"(a), "l"(b));
}
__device__ __forceinline__ ull pk(float x, float y) {
    ull v; asm("mov.b64 %0, {%1, %2};" : "=l"(v) : "f"(x), "f"(y)); return v;
}
__device__ __forceinline__ float2 upk(ull v) {
    float2 r; asm("mov.b64 {%0, %1}, %2;" : "=f"(r.x), "=f"(r.y) : "l"(v)); return r;
}

// thread tile: rows ty*4..ty*4+3  x  outputs {4tx+2p, 4tx+2p+1} and {32+4tx+2p, ...}
// acc[r*4 + g*2 + p] = f32x2 over outputs (o, o+1), o = 4*tx + 32*g + 2*p, row = ty*4+r

// ---------------------------------------------------------------------------
// adj pre-kernel
// ---------------------------------------------------------------------------
__global__ void gkt_adj(const int* __restrict__ qt, const float* __restrict__ onehot,
                        const float* __restrict__ graphs) {
    __shared__ int nz[C_DIM];
    __shared__ int wcnt[32];
    __shared__ int woff[33];
    const int t = threadIdx.x, wid = t >> 5, lane = t & 31;
    const int q0 = qt[0];
    const bool on = (onehot[(long)q0 * C_DIM + t] > 0.5f);
    unsigned bal = __ballot_sync(0xffffffffu, on);
    if (lane == 0) wcnt[wid] = __popc(bal);
    __syncthreads();
    if (t == 0) { int s = 0; for (int w = 0; w < 32; ++w) { woff[w] = s; s += wcnt[w]; } woff[32] = s; }
    __syncthreads();
    if (on) nz[woff[wid] + __popc(bal & ((1u << lane) - 1u))] = t;
    __syncthreads();
    const int n = woff[32];
    const float denom = fmaxf((float)n, 1.f);
#pragma unroll
    for (int k = 0; k < 2; ++k) {
        float s = 0.f;
        for (int idx = 0; idx < n; ++idx)
            s += graphs[k * C_DIM * C_DIM + nz[idx] * C_DIM + t];
        g_adj[k * C_DIM + t] = clipf(s / denom, -5.f, 5.f);
    }
}

// ---------------------------------------------------------------------------
// helpers
// ---------------------------------------------------------------------------

// Stage a 64x64 weight tile into WD, natural layout (row = 64 floats).
__device__ __forceinline__ void stage_w(float* __restrict__ WD, const float* __restrict__ src,
                                        int rstride, int t) {
#pragma unroll
    for (int i = t; i < 64 * 16; i += TPB) {
        int kk = i >> 4, o4 = i & 15;
        *reinterpret_cast<float4*>(WD + kk * 64 + o4 * 4) = ldg4(src + kk * rstride + o4 * 4);
    }
}

// acc += A(rows) x W(outs): per k-step 1 LDS.128 (4 rows) + 2 LDS.128 (weights) + 16 FFMA2.
__device__ __forceinline__ void gemm_acc(const float* __restrict__ A, const float* __restrict__ WD,
                                         int ty, int tx, ull acc[16]) {
    const float* Ab = A + ty * 4;
    const ulonglong2* Wb = reinterpret_cast<const ulonglong2*>(WD) + tx;   // row = 16 u2
#pragma unroll 4
    for (int kk = 0; kk < 64; ++kk) {
        float4 av = *reinterpret_cast<const float4*>(Ab + kk * PAD);
        ull ad[4] = { pk(av.x, av.x), pk(av.y, av.y), pk(av.z, av.z), pk(av.w, av.w) };
        ulonglong2 w0 = Wb[kk * 16];        // floats 4tx .. 4tx+3
        ulonglong2 w1 = Wb[kk * 16 + 8];    // floats 32+4tx .. 32+4tx+3
#pragma unroll
        for (int r = 0; r < 4; ++r) {
            ffma2(acc[r * 4 + 0], ad[r], w0.x);
            ffma2(acc[r * 4 + 1], ad[r], w0.y);
            ffma2(acc[r * 4 + 2], ad[r], w1.x);
            ffma2(acc[r * 4 + 3], ad[r], w1.y);
        }
    }
}

__device__ __forceinline__ void init_bias(ull acc[16], const float* __restrict__ b1p,
                                          const float* __restrict__ b2p, int tx) {
#pragma unroll
    for (int g = 0; g < 2; ++g)
#pragma unroll
    for (int p = 0; p < 2; ++p) {
        int o = 4 * tx + 32 * g + 2 * p;
        float vx = __ldg(b1p + o), vy = __ldg(b1p + o + 1);
        if (b2p) { vx += __ldg(b2p + o); vy += __ldg(b2p + o + 1); }
        ull pv = pk(vx, vy);
        acc[g * 2 + p] = pv; acc[4 + g * 2 + p] = pv;
        acc[8 + g * 2 + p] = pv; acc[12 + g * 2 + p] = pv;
    }
}

// ---------------------------------------------------------------------------
// fused main kernel
// ---------------------------------------------------------------------------
__global__ __launch_bounds__(TPB, 1) void gkt_main(
    const int*   __restrict__ qt,     const float* __restrict__ ht,
    const float* __restrict__ onehot, const float* __restrict__ kc,
    const float* __restrict__ nw_ptr,
    const float* __restrict__ Ws1, const float* __restrict__ bs1,
    const float* __restrict__ Ws2, const float* __restrict__ bs2,
    const float* __restrict__ Wn1, const float* __restrict__ bn1,
    const float* __restrict__ Wn2, const float* __restrict__ bn2,
    const float* __restrict__ ea_w,
    const float* __restrict__ We,  const float* __restrict__ be,
    const float* __restrict__ Wa,  const float* __restrict__ ba,
    const float* __restrict__ W_ih, const float* __restrict__ b_ih,
    const float* __restrict__ W_hh, const float* __restrict__ b_hh,
    const float* __restrict__ Wp,  const float* __restrict__ bp,
    float* __restrict__ out)
{
    extern __shared__ float sm[];
    float* XT = sm + SM_XT;
    float* XH = sm + SM_XH;
    float* WD = sm + SM_WD;
    float* B1 = sm + SM_B1;
    float* B2 = sm + SM_B2;
    float* B3 = sm + SM_B3;
    float* B4 = XT;                 // XT region reused after self fix-up
    float* tmp = WD;                // fix-up scratch
    int*   mlist = (int*)(WD + 64);
    int*   mcnt  = (int*)(WD + 192);

    const int t  = threadIdx.x;
    const int tx = t & 7, ty = t >> 3;        // rows = ty*4 .. ty*4+3
    const int row0 = blockIdx.x * TILE_R;
    const int b  = row0 >> 10;
    const int c0 = row0 & (C_DIM - 1);
    const int q  = __ldg(&qt[b]);

    // ---- stage X transposed: XT clipped(+-5), XH raw ht ----
#pragma unroll
    for (int i = t; i < TILE_R * 64; i += TPB) {
        int row = i >> 6, k = i & 63;
        float hv = ht[(row0 + row) * 64 + k];
        XH[k * PAD + row] = hv;
        XT[k * PAD + row] = clipf(hv, -5.f, 5.f);
        XT[(64 + k) * PAD + row] = clipf(kc[(c0 + row) * 64 + k], -5.f, 5.f);
    }

    ull acc[16];
    const float wcl = clipf(__ldg(nw_ptr), 0.1f, 0.9f);

    // ================= stage 1: H1(k=0) = relu(X @ Wn1[0][128:256]) ========
    init_bias(acc, bn1, nullptr, tx);
    __syncthreads();
    stage_w(WD, Wn1 + (0 * 256 + 128) * 64, 64, t);
    __syncthreads();
    gemm_acc(XT, WD, ty, tx, acc);
    __syncthreads();
    stage_w(WD, Wn1 + (0 * 256 + 192) * 64, 64, t);
    __syncthreads();
    gemm_acc(XT + 64 * PAD, WD, ty, tx, acc);
#pragma unroll
    for (int r = 0; r < 4; ++r) {
        int row = ty * 4 + r;
#pragma unroll
        for (int g = 0; g < 2; ++g)
#pragma unroll
        for (int p = 0; p < 2; ++p) {
            int o = 4 * tx + 32 * g + 2 * p;
            float2 v = upk(acc[r * 4 + g * 2 + p]);
            B1[o * PAD + row]       = fmaxf(v.x, 0.f);
            B1[(o + 1) * PAD + row] = fmaxf(v.y, 0.f);
        }
    }

    // ================= stage 2: nf0 = clip5(aj0 * clip5(relu(H1 @ Wn2[0]))) =
    init_bias(acc, bn2, nullptr, tx);
    __syncthreads();
    stage_w(WD, Wn2, 64, t);
    __syncthreads();
    gemm_acc(B1, WD, ty, tx, acc);
#pragma unroll
    for (int r = 0; r < 4; ++r) {
        int row = ty * 4 + r;
        float a0 = __ldg(&g_adj[c0 + row]);
#pragma unroll
        for (int g = 0; g < 2; ++g)
#pragma unroll
        for (int p = 0; p < 2; ++p) {
            int o = 4 * tx + 32 * g + 2 * p;
            float2 v = upk(acc[r * 4 + g * 2 + p]);
            float nb0x = fminf(fmaxf(v.x, 0.f), 5.f);
            float nb0y = fminf(fmaxf(v.y, 0.f), 5.f);
            B2[o * PAD + row]       = clipf(a0 * nb0x, -5.f, 5.f);
            B2[(o + 1) * PAD + row] = clipf(a0 * nb0y, -5.f, 5.f);
        }
    }

    // ================= stage 3: H1(k=1) ====================================
    init_bias(acc, bn1 + 64, nullptr, tx);
    __syncthreads();
    stage_w(WD, Wn1 + (1 * 256 + 128) * 64, 64, t);
    __syncthreads();
    gemm_acc(XT, WD, ty, tx, acc);
    __syncthreads();
    stage_w(WD, Wn1 + (1 * 256 + 192) * 64, 64, t);
    __syncthreads();
    gemm_acc(XT + 64 * PAD, WD, ty, tx, acc);
#pragma unroll
    for (int r = 0; r < 4; ++r) {
        int row = ty * 4 + r;
#pragma unroll
        for (int g = 0; g < 2; ++g)
#pragma unroll
        for (int p = 0; p < 2; ++p) {
            int o = 4 * tx + 32 * g + 2 * p;
            float2 v = upk(acc[r * 4 + g * 2 + p]);
            B1[o * PAD + row]       = fmaxf(v.x, 0.f);
            B1[(o + 1) * PAD + row] = fmaxf(v.y, 0.f);
        }
    }

    // ================= stage 4: nf = clip5(w*nf0 + (1-w)*aj1*nb1) ==========
    init_bias(acc, bn2 + 64, nullptr, tx);
    __syncthreads();
    stage_w(WD, Wn2 + 64 * 64, 64, t);
    __syncthreads();
    gemm_acc(B1, WD, ty, tx, acc);
#pragma unroll
    for (int r = 0; r < 4; ++r) {
        int row = ty * 4 + r;
        float a1 = __ldg(&g_adj[C_DIM + c0 + row]);
#pragma unroll
        for (int g = 0; g < 2; ++g)
#pragma unroll
        for (int p = 0; p < 2; ++p) {
            int o = 4 * tx + 32 * g + 2 * p;
            float2 v = upk(acc[r * 4 + g * 2 + p]);
            float nb1x = fminf(fmaxf(v.x, 0.f), 5.f);
            float nb1y = fminf(fmaxf(v.y, 0.f), 5.f);
            float nf0x = B2[o * PAD + row];
            float nf0y = B2[(o + 1) * PAD + row];
            B2[o * PAD + row]       = clipf(wcl * nf0x + (1.f - wcl) * a1 * nb1x, -5.f, 5.f);
            B2[(o + 1) * PAD + row] = clipf(wcl * nf0y + (1.f - wcl) * a1 * nb1y, -5.f, 5.f);
        }
    }

    // ================= stage 5: masked-row self-MLP fix-up ==================
    __syncthreads();
    if (t == 0) *mcnt = 0;
    __syncthreads();
    if (t < TILE_R) {
        float m = __ldg(&onehot[(long)q * C_DIM + c0 + t]);
        if (m > 0.5f) { int pos = atomicAdd(mcnt, 1); mlist[pos] = t; }
    }
    __syncthreads();
    const int nm = *mcnt;
    for (int idx = 0; idx < nm; ++idx) {
        int row = mlist[idx];
        if (t < 64) {
            float a = __ldg(bs1 + t);
            for (int k = 0; k < 64; ++k)   a += XH[k * PAD + row] * __ldg(Ws1 + k * 64 + t);
            for (int k = 64; k < 128; ++k) a += XT[k * PAD + row] * __ldg(Ws1 + k * 64 + t);
            tmp[t] = fmaxf(a, 0.f);
        }
        __syncthreads();
        if (t < 64) {
            float a = __ldg(bs2 + t);
            for (int k = 0; k < 64; ++k) a += tmp[k] * __ldg(Ws2 + k * 64 + t);
            B2[t * PAD + row] = clipf(fmaxf(a, 0.f), -10.f, 10.f);
        }
        __syncthreads();
    }
    // B2 now holds m_next (mn)

    // ================= stage 6: sigE = sigmoid(mn @ We + be) -> B1 =========
    init_bias(acc, be, nullptr, tx);
    __syncthreads();
    stage_w(WD, We, 64, t);
    __syncthreads();
    gemm_acc(B2, WD, ty, tx, acc);
#pragma unroll
    for (int r = 0; r < 4; ++r) {
        int row = ty * 4 + r;
#pragma unroll
        for (int g = 0; g < 2; ++g)
#pragma unroll
        for (int p = 0; p < 2; ++p) {
            int o = 4 * tx + 32 * g + 2 * p;
            float2 v = upk(acc[r * 4 + g * 2 + p]);
            B1[o * PAD + row]       = sigm(v.x);
            B1[(o + 1) * PAD + row] = sigm(v.y);
        }
    }

    // ================= stage 7: res = mn - g*sigE*mn + g*tanh(mn@Wa+ba) -> B3
    init_bias(acc, ba, nullptr, tx);
    __syncthreads();
    stage_w(WD, Wa, 64, t);
    __syncthreads();
    gemm_acc(B2, WD, ty, tx, acc);
#pragma unroll
    for (int r = 0; r < 4; ++r) {
        int row = ty * 4 + r;
        float gg = __ldg(&ea_w[c0 + row]);
#pragma unroll
        for (int g = 0; g < 2; ++g)
#pragma unroll
        for (int p = 0; p < 2; ++p) {
            int o = 4 * tx + 32 * g + 2 * p;
            float2 v = upk(acc[r * 4 + g * 2 + p]);
            float mnx = B2[o * PAD + row],       sgx = B1[o * PAD + row];
            float mny = B2[(o + 1) * PAD + row], sgy = B1[(o + 1) * PAD + row];
            B3[o * PAD + row]       = mnx - gg * sgx * mnx + gg * tanhf(v.x);
            B3[(o + 1) * PAD + row] = mny - gg * sgy * mny + gg * tanhf(v.y);
        }
    }

    // ================= stage 8: r gate -> B1 ================================
    init_bias(acc, b_ih, b_hh, tx);
    __syncthreads();
    stage_w(WD, W_ih, 192, t);
    __syncthreads();
    gemm_acc(B3, WD, ty, tx, acc);
    __syncthreads();
    stage_w(WD, W_hh, 192, t);
    __syncthreads();
    gemm_acc(XH, WD, ty, tx, acc);
#pragma unroll
    for (int r = 0; r < 4; ++r) {
        int row = ty * 4 + r;
#pragma unroll
        for (int g = 0; g < 2; ++g)
#pragma unroll
        for (int p = 0; p < 2; ++p) {
            int o = 4 * tx + 32 * g + 2 * p;
            float2 v = upk(acc[r * 4 + g * 2 + p]);
            B1[o * PAD + row]       = sigm(v.x);
            B1[(o + 1) * PAD + row] = sigm(v.y);
        }
    }

    // ================= stage 9: z gate -> B2 (mn dead) ======================
    init_bias(acc, b_ih + 64, b_hh + 64, tx);
    __syncthreads();
    stage_w(WD, W_ih + 64, 192, t);
    __syncthreads();
    gemm_acc(B3, WD, ty, tx, acc);
    __syncthreads();
    stage_w(WD, W_hh + 64, 192, t);
    __syncthreads();
    gemm_acc(XH, WD, ty, tx, acc);
#pragma unroll
    for (int r = 0; r < 4; ++r) {
        int row = ty * 4 + r;
#pragma unroll
        for (int g = 0; g < 2; ++g)
#pragma unroll
        for (int p = 0; p < 2; ++p) {
            int o = 4 * tx + 32 * g + 2 * p;
            float2 v = upk(acc[r * 4 + g * 2 + p]);
            B2[o * PAD + row]       = sigm(v.x);
            B2[(o + 1) * PAD + row] = sigm(v.y);
        }
    }

    // ================= stage 10a: hn = ht@Whhn + bhhn -> B4 (XT reuse) =====
    init_bias(acc, b_hh + 128, nullptr, tx);
    __syncthreads();
    stage_w(WD, W_hh + 128, 192, t);
    __syncthreads();
    gemm_acc(XH, WD, ty, tx, acc);
#pragma unroll
    for (int r = 0; r < 4; ++r) {
        int row = ty * 4 + r;
#pragma unroll
        for (int g = 0; g < 2; ++g)
#pragma unroll
        for (int p = 0; p < 2; ++p) {
            int o = 4 * tx + 32 * g + 2 * p;
            float2 v = upk(acc[r * 4 + g * 2 + p]);
            B4[o * PAD + row]       = v.x;
            B4[(o + 1) * PAD + row] = v.y;
        }
    }

    // ================= stage 10b: n, h_next -> B1 ==========================
    init_bias(acc, b_ih + 128, nullptr, tx);
    __syncthreads();
    stage_w(WD, W_ih + 128, 192, t);
    __syncthreads();
    gemm_acc(B3, WD, ty, tx, acc);
#pragma unroll
    for (int r = 0; r < 4; ++r) {
        int row = ty * 4 + r;
#pragma unroll
        for (int g = 0; g < 2; ++g)
#pragma unroll
        for (int p = 0; p < 2; ++p) {
            int o = 4 * tx + 32 * g + 2 * p;
            float2 v = upk(acc[r * 4 + g * 2 + p]);
            float hnx = B4[o * PAD + row],       hny = B4[(o + 1) * PAD + row];
            float rrx = B1[o * PAD + row],       rry = B1[(o + 1) * PAD + row];
            float zzx = B2[o * PAD + row],       zzy = B2[(o + 1) * PAD + row];
            float hvx = XH[o * PAD + row],       hvy = XH[(o + 1) * PAD + row];
            float nx = tanhf(v.x + rrx * hnx);
            float ny = tanhf(v.y + rry * hny);
            B1[o * PAD + row]       = (1.f - zzx) * nx + zzx * hvx;
            B1[(o + 1) * PAD + row] = (1.f - zzy) * ny + zzy * hvy;
        }
    }

    // ================= stage 11: y = sigm(h_next @ Wp + bp) ================
    __syncthreads();
    {
        int row = t >> 1, half = t & 1;
        float s = 0.f;
        const float* hb = B1 + half * 32 * PAD + row;
#pragma unroll
        for (int o = 0; o < 32; ++o)
            s += hb[o * PAD] * __ldg(Wp + half * 32 + o);
        s += __shfl_xor_sync(0xffffffffu, s, 1);
        if (half == 0)
            out[row0 + row] = sigm(s + __ldg(bp));
    }
}

extern "C" void kernel_launch(void* const* d_in, const int* in_sizes, int n_in,
                              void* d_out, int out_size) {
    const int*   qt     = (const int*)  d_in[1];
    const float* ht     = (const float*)d_in[2];
    const float* onehot = (const float*)d_in[3];
    const float* kc     = (const float*)d_in[4];
    const float* graphs = (const float*)d_in[5];
    const float* nw     = (const float*)d_in[6];
    const float* Ws1    = (const float*)d_in[7];
    const float* bs1    = (const float*)d_in[8];
    const float* Ws2    = (const float*)d_in[9];
    const float* bs2    = (const float*)d_in[10];
    const float* Wn1    = (const float*)d_in[11];
    const float* bn1    = (const float*)d_in[12];
    const float* Wn2    = (const float*)d_in[13];
    const float* bn2    = (const float*)d_in[14];
    const float* ea_w   = (const float*)d_in[15];
    const float* We     = (const float*)d_in[16];
    const float* be     = (const float*)d_in[17];
    const float* Wa     = (const float*)d_in[18];
    const float* ba     = (const float*)d_in[19];
    const float* W_ih   = (const float*)d_in[20];
    const float* b_ih   = (const float*)d_in[21];
    const float* W_hh   = (const float*)d_in[22];
    const float* b_hh   = (const float*)d_in[23];
    const float* Wp     = (const float*)d_in[24];
    const float* bp     = (const float*)d_in[25];
    float* out = (float*)d_out;

    gkt_adj<<<1, 1024>>>(qt, onehot, graphs);

    const int smem_bytes = SM_TOT * (int)sizeof(float);   // 219136 B
    cudaFuncSetAttribute(gkt_main, cudaFuncAttributeMaxDynamicSharedMemorySize, smem_bytes);
    const int nrows = 256 * C_DIM;
    gkt_main<<<nrows / TILE_R, TPB, smem_bytes>>>(
        qt, ht, onehot, kc, nw,
        Ws1, bs1, Ws2, bs2, Wn1, bn1, Wn2, bn2,
        ea_w, We, be, Wa, ba, W_ih, b_ih, W_hh, b_hh, Wp, bp,
        out);
}